// round 8
// baseline (speedup 1.0000x reference)
#include <cuda_runtime.h>
#include <cuda_bf16.h>
#include <cstdint>

// AttentionBlock fused kernel, sm_103a. Round 7:
// R4 algebra (M8=WqWk^T, W9=WvWo; G=X@M8, S=G@X^T, P=softmax, T=P@X, out=T@W9+b9+x)
// with M=128 CTAs (2 bh rows), 64x64 warp tiles (128 B LDSM/mma), 1 CTA/SM.

#define CH    256
#define LDH   264   // bf16 tile row stride in halves
#define LDP   72    // bf16 P tile stride

__device__ __nv_bfloat16 g_M8[CH * CH];   // (Wq @ Wk^T), stored [k][n]
__device__ __nv_bfloat16 g_W9[CH * CH];   // (Wv @ Wo),   stored [k][n]
__device__ float g_b9[CH];                // bv @ Wo + bo
__device__ float g_w8[CH];                // Wk @ bq
__device__ float g_s8;                    // bk . bq

// ---- setup: fused weight products (fp32 accum, bf16 out) ----
__global__ void setup_gemm_kernel(const float* __restrict__ Wq, const float* __restrict__ Wk,
                                  const float* __restrict__ Wv, const float* __restrict__ Wo) {
    __shared__ float As[32][33];
    __shared__ float Bs[32][33];
    const int tid = threadIdx.x;
    const int tx = tid & 31, ty = tid >> 5;
    const int a0 = blockIdx.y * 32, b0 = blockIdx.x * 32;
    const int z = blockIdx.z;
    const float* A = z ? Wv : Wq;

    float acc[4] = {0.f, 0.f, 0.f, 0.f};
    for (int d0 = 0; d0 < CH; d0 += 32) {
        {
            int i = tid >> 3, j = (tid & 7) * 4;
            float4 v = *(const float4*)(A + (a0 + i) * CH + d0 + j);
            As[i][j] = v.x; As[i][j + 1] = v.y; As[i][j + 2] = v.z; As[i][j + 3] = v.w;
        }
        if (z == 0) {   // Bs[dd][c] = Wk[b0+c][d0+dd]
            int i = tid >> 3, j = (tid & 7) * 4;
            float4 v = *(const float4*)(Wk + (b0 + i) * CH + d0 + j);
            Bs[j][i] = v.x; Bs[j + 1][i] = v.y; Bs[j + 2][i] = v.z; Bs[j + 3][i] = v.w;
        } else {        // Bs[dd][c] = Wo[d0+dd][b0+c]
            int j = tid >> 3, i = (tid & 7) * 4;
            float4 v = *(const float4*)(Wo + (d0 + j) * CH + b0 + i);
            Bs[j][i] = v.x; Bs[j][i + 1] = v.y; Bs[j][i + 2] = v.z; Bs[j][i + 3] = v.w;
        }
        __syncthreads();
        #pragma unroll
        for (int dd = 0; dd < 32; dd++) {
            float b = Bs[dd][tx];
            #pragma unroll
            for (int r = 0; r < 4; r++) acc[r] += As[ty + 8 * r][dd] * b;
        }
        __syncthreads();
    }
    __nv_bfloat16* dst = z ? g_W9 : g_M8;
    #pragma unroll
    for (int r = 0; r < 4; r++)
        dst[(a0 + ty + 8 * r) * CH + b0 + tx] = __float2bfloat16(acc[r]);
}

__global__ void setup_vec_kernel(const float* __restrict__ Wk, const float* __restrict__ Wo,
                                 const float* __restrict__ bq, const float* __restrict__ bk,
                                 const float* __restrict__ bv, const float* __restrict__ bo) {
    int c = threadIdx.x;
    float w8 = 0.f, b9 = 0.f;
    for (int d = 0; d < CH; d++) {
        w8 += Wk[c * CH + d] * bq[d];
        b9 += bv[d] * Wo[d * CH + c];
    }
    g_w8[c] = w8;
    g_b9[c] = b9 + bo[c];
    if (c == 0) {
        float s = 0.f;
        for (int d = 0; d < CH; d++) s += bk[d] * bq[d];
        g_s8 = s;
    }
}

// ---- mma.sync helpers ----
__device__ __forceinline__ uint32_t smem_u32(const void* p) {
    return (uint32_t)__cvta_generic_to_shared(p);
}
__device__ __forceinline__ void ldm_x4(uint32_t addr, uint32_t& a0, uint32_t& a1,
                                       uint32_t& a2, uint32_t& a3) {
    asm volatile("ldmatrix.sync.aligned.m8n8.x4.shared.b16 {%0,%1,%2,%3}, [%4];"
                 : "=r"(a0), "=r"(a1), "=r"(a2), "=r"(a3) : "r"(addr));
}
__device__ __forceinline__ void ldm_x4t(uint32_t addr, uint32_t& b0, uint32_t& b1,
                                        uint32_t& b2, uint32_t& b3) {
    asm volatile("ldmatrix.sync.aligned.m8n8.x4.trans.shared.b16 {%0,%1,%2,%3}, [%4];"
                 : "=r"(b0), "=r"(b1), "=r"(b2), "=r"(b3) : "r"(addr));
}
__device__ __forceinline__ void mma_bf16(float c[4],
                                         uint32_t a0, uint32_t a1, uint32_t a2, uint32_t a3,
                                         uint32_t b0, uint32_t b1) {
    asm volatile("mma.sync.aligned.m16n8k16.row.col.f32.bf16.bf16.f32 "
                 "{%0,%1,%2,%3}, {%4,%5,%6,%7}, {%8,%9}, {%0,%1,%2,%3};"
                 : "+f"(c[0]), "+f"(c[1]), "+f"(c[2]), "+f"(c[3])
                 : "r"(a0), "r"(a1), "r"(a2), "r"(a3), "r"(b0), "r"(b1));
}
__device__ __forceinline__ void cp16(void* smem, const void* gmem) {
    asm volatile("cp.async.cg.shared.global [%0], [%1], 16;"
                 :: "r"(smem_u32(smem)), "l"(gmem));
}

// Stream a [32 k][256 n] bf16 weight chunk into smem (strided LDH rows).
__device__ __forceinline__ void load_w_chunk32(__nv_bfloat16* dst,
                                               const __nv_bfloat16* src, int tid) {
    #pragma unroll
    for (int i = 0; i < 4; i++) {
        int j = tid + i * 256;     // 1024 x 16B
        cp16(dst + (j >> 5) * LDH + (j & 31) * 8, src + j * 8);
    }
    asm volatile("cp.async.commit_group;");
}

// Chunked GEMM: acc[64x64 warp tile] = A[128x256](smem) @ W[256x256](gmem).
__device__ __forceinline__ void gemm_w(const __nv_bfloat16* __restrict__ Wg,
                                       const __nv_bfloat16* sA, int ldA,
                                       __nv_bfloat16* sW0, __nv_bfloat16* sW1,
                                       float acc[4][8][4],
                                       int tid, int lane, int r0, int nb) {
    #pragma unroll
    for (int mt = 0; mt < 4; mt++)
        #pragma unroll
        for (int nt = 0; nt < 8; nt++)
            acc[mt][nt][0] = acc[mt][nt][1] = acc[mt][nt][2] = acc[mt][nt][3] = 0.f;

    load_w_chunk32(sW0, Wg, tid);
    #pragma unroll 1
    for (int kc = 0; kc < 8; kc++) {
        __nv_bfloat16* wbuf = (kc & 1) ? sW1 : sW0;
        if (kc < 7) {
            load_w_chunk32((kc & 1) ? sW0 : sW1, Wg + (kc + 1) * 32 * CH, tid);
            asm volatile("cp.async.wait_group 1;");
        } else {
            asm volatile("cp.async.wait_group 0;");
        }
        __syncthreads();
        #pragma unroll
        for (int ks = 0; ks < 2; ks++) {
            int kof = kc * 32 + ks * 16;
            uint32_t a[4][4];
            #pragma unroll
            for (int mt = 0; mt < 4; mt++)
                ldm_x4(smem_u32(sA + (r0 + mt * 16 + (lane & 15)) * ldA
                                + kof + ((lane >> 4) << 3)),
                       a[mt][0], a[mt][1], a[mt][2], a[mt][3]);
            #pragma unroll
            for (int nt16 = 0; nt16 < 4; nt16++) {
                uint32_t b0, b1, b2, b3;
                ldm_x4t(smem_u32(wbuf + (ks * 16 + (lane & 15)) * LDH
                                 + nb + nt16 * 16 + ((lane >> 4) << 3)),
                        b0, b1, b2, b3);
                #pragma unroll
                for (int mt = 0; mt < 4; mt++) {
                    mma_bf16(acc[mt][2 * nt16],     a[mt][0], a[mt][1], a[mt][2], a[mt][3], b0, b1);
                    mma_bf16(acc[mt][2 * nt16 + 1], a[mt][0], a[mt][1], a[mt][2], a[mt][3], b2, b3);
                }
            }
        }
        __syncthreads();
    }
}

// SMEM: sX 67584 + sG 67584 + sW 33792 + sP 18432 + sC 512 + sBias 1024 = 188928
#define SMEM_BYTES 188928

__global__ void __launch_bounds__(256, 1)
attn_kernel(const float* __restrict__ x, float* __restrict__ out)
{
    extern __shared__ char smem_raw[];
    __nv_bfloat16* sX  = (__nv_bfloat16*)smem_raw;             // [128][LDH]
    __nv_bfloat16* sG  = sX + 128 * LDH;                       // [128][LDH]
    __nv_bfloat16* sW0 = sG + 128 * LDH;                       // [32][LDH]
    __nv_bfloat16* sW1 = sW0 + 32 * LDH;                       // [32][LDH]
    __nv_bfloat16* sP  = sW1 + 32 * LDH;                       // [128][LDP]
    float*         sC  = (float*)(sP + 128 * LDP);             // [128]
    float*      sBias  = sC + 128;                             // [256]

    const int tid  = threadIdx.x;
    const int wid  = tid >> 5;
    const int lane = tid & 31;
    const int grp  = lane >> 2;
    const int tig  = lane & 3;

    const size_t base = (size_t)blockIdx.x * 128 * CH;
    const float* xrow = x   + base;
    float*       orow = out + base;

    // ---------------- Phase 0: bias + x tile (fp32 -> bf16) + c_j ----------------
    sBias[tid] = g_b9[tid];
    {
        const float4* xv = (const float4*)xrow;
        #pragma unroll
        for (int t = 0; t < 32; t++) {
            int i = tid + t * 256;             // 8192 float4
            int row = i >> 6;
            int colf = (i & 63) * 4;
            float4 v = xv[i];
            __nv_bfloat162* d = (__nv_bfloat162*)(sX + row * LDH + colf);
            d[0] = __floats2bfloat162_rn(v.x, v.y);
            d[1] = __floats2bfloat162_rn(v.z, v.w);
        }
    }
    // c_j = x_j . w8 + s8 (fp32 from gmem; 2 threads per row)
    {
        int row = tid >> 1, hh = tid & 1;
        const float4* xv = (const float4*)(xrow + row * CH + hh * 128);
        float s = 0.f;
        #pragma unroll
        for (int j = 0; j < 32; j++) {
            float4 v = xv[j];
            int c = hh * 128 + j * 4;
            s += v.x * g_w8[c] + v.y * g_w8[c + 1] + v.z * g_w8[c + 2] + v.w * g_w8[c + 3];
        }
        s += __shfl_xor_sync(0xffffffffu, s, 1);
        if (hh == 0) sC[row] = s + g_s8;
    }
    __syncthreads();

    const int r0 = (wid >> 2) * 64;   // warp's 64 rows
    const int nb = (wid & 3) * 64;    // warp's 64 cols

    float acc[4][8][4];

    // ---------------- G = X @ M8 -> sG ----------------
    gemm_w(g_M8, sX, LDH, sW0, sW1, acc, tid, lane, r0, nb);
    #pragma unroll
    for (int mt = 0; mt < 4; mt++)
        #pragma unroll
        for (int nt = 0; nt < 8; nt++) {
            int col = nb + nt * 8 + tig * 2;
            int ra = r0 + mt * 16 + grp;
            *(__nv_bfloat162*)(sG + ra * LDH + col) =
                __floats2bfloat162_rn(acc[mt][nt][0], acc[mt][nt][1]);
            *(__nv_bfloat162*)(sG + (ra + 8) * LDH + col) =
                __floats2bfloat162_rn(acc[mt][nt][2], acc[mt][nt][3]);
        }
    __syncthreads();

    // ------- S = (G X^T + c_j)*scale over block-diagonal, softmax -> P -------
    // 8 warps; warp handles rows [wid*16, wid*16+16), block = wid>>2, cols blk*64..+64
    {
        const int r0s = wid * 16;
        const int blk = wid >> 2;
        const int j0 = blk * 64;
        float sa[8][4];
        #pragma unroll
        for (int nt = 0; nt < 8; nt++)
            sa[nt][0] = sa[nt][1] = sa[nt][2] = sa[nt][3] = 0.f;
        #pragma unroll
        for (int ks = 0; ks < 16; ks++) {
            uint32_t a0, a1, a2, a3;
            ldm_x4(smem_u32(sG + (r0s + (lane & 15)) * LDH + ks * 16 + ((lane >> 4) << 3)),
                   a0, a1, a2, a3);
            #pragma unroll
            for (int nt16 = 0; nt16 < 4; nt16++) {
                uint32_t b0, b1, b2, b3;
                ldm_x4(smem_u32(sX + (j0 + nt16 * 16 + ((lane >> 4) << 3) + (lane & 7)) * LDH
                                + ks * 16 + (((lane >> 3) & 1) << 3)),
                       b0, b1, b2, b3);
                mma_bf16(sa[2 * nt16],     a0, a1, a2, a3, b0, b1);
                mma_bf16(sa[2 * nt16 + 1], a0, a1, a2, a3, b2, b3);
            }
        }
        const float SCALE = 1.0f / (256.0f * 16.0f * 0.70710678118654752f);
        float v0[16], v1[16];
        #pragma unroll
        for (int nt = 0; nt < 8; nt++) {
            int col = nt * 8 + tig * 2;
            float c0 = sC[j0 + col], c1 = sC[j0 + col + 1];
            v0[2 * nt] = (sa[nt][0] + c0) * SCALE; v0[2 * nt + 1] = (sa[nt][1] + c1) * SCALE;
            v1[2 * nt] = (sa[nt][2] + c0) * SCALE; v1[2 * nt + 1] = (sa[nt][3] + c1) * SCALE;
        }
        float m0 = v0[0], m1 = v1[0];
        #pragma unroll
        for (int i = 1; i < 16; i++) { m0 = fmaxf(m0, v0[i]); m1 = fmaxf(m1, v1[i]); }
        m0 = fmaxf(m0, __shfl_xor_sync(0xffffffffu, m0, 1));
        m0 = fmaxf(m0, __shfl_xor_sync(0xffffffffu, m0, 2));
        m1 = fmaxf(m1, __shfl_xor_sync(0xffffffffu, m1, 1));
        m1 = fmaxf(m1, __shfl_xor_sync(0xffffffffu, m1, 2));
        float s0 = 0.f, s1 = 0.f;
        #pragma unroll
        for (int i = 0; i < 16; i++) {
            v0[i] = __expf(v0[i] - m0); s0 += v0[i];
            v1[i] = __expf(v1[i] - m1); s1 += v1[i];
        }
        s0 += __shfl_xor_sync(0xffffffffu, s0, 1);
        s0 += __shfl_xor_sync(0xffffffffu, s0, 2);
        s1 += __shfl_xor_sync(0xffffffffu, s1, 1);
        s1 += __shfl_xor_sync(0xffffffffu, s1, 2);
        float i0 = 1.0f / s0, i1 = 1.0f / s1;
        int ra = r0s + grp, rb = ra + 8;
        #pragma unroll
        for (int nt = 0; nt < 8; nt++) {
            *(__nv_bfloat162*)(sP + ra * LDP + nt * 8 + tig * 2) =
                __floats2bfloat162_rn(v0[2 * nt] * i0, v0[2 * nt + 1] * i0);
            *(__nv_bfloat162*)(sP + rb * LDP + nt * 8 + tig * 2) =
                __floats2bfloat162_rn(v1[2 * nt] * i1, v1[2 * nt + 1] * i1);
        }
    }
    __syncthreads();

    // ------- T = P_blk @ X_blk -> sG (per-block K=64; G dead after S) -------
    {
        const int blk = wid >> 2;          // row block: rows r0..r0+63, K = X rows blk*64..
        #pragma unroll
        for (int mt = 0; mt < 4; mt++)
            #pragma unroll
            for (int nt = 0; nt < 8; nt++)
                acc[mt][nt][0] = acc[mt][nt][1] = acc[mt][nt][2] = acc[mt][nt][3] = 0.f;
        #pragma unroll
        for (int ks = 0; ks < 4; ks++) {
            uint32_t a[4][4];
            #pragma unroll
            for (int mt = 0; mt < 4; mt++)
                ldm_x4(smem_u32(sP + (r0 + mt * 16 + (lane & 15)) * LDP
                                + ks * 16 + ((lane >> 4) << 3)),
                       a[mt][0], a[mt][1], a[mt][2], a[mt][3]);
            #pragma unroll
            for (int nt16 = 0; nt16 < 4; nt16++) {
                uint32_t b0, b1, b2, b3;
                ldm_x4t(smem_u32(sX + (blk * 64 + ks * 16 + (lane & 15)) * LDH
                                 + nb + nt16 * 16 + ((lane >> 4) << 3)),
                        b0, b1, b2, b3);
                #pragma unroll
                for (int mt = 0; mt < 4; mt++) {
                    mma_bf16(acc[mt][2 * nt16],     a[mt][0], a[mt][1], a[mt][2], a[mt][3], b0, b1);
                    mma_bf16(acc[mt][2 * nt16 + 1], a[mt][0], a[mt][1], a[mt][2], a[mt][3], b2, b3);
                }
            }
        }
        #pragma unroll
        for (int mt = 0; mt < 4; mt++)
            #pragma unroll
            for (int nt = 0; nt < 8; nt++) {
                int col = nb + nt * 8 + tig * 2;
                int ra = r0 + mt * 16 + grp;
                *(__nv_bfloat162*)(sG + ra * LDH + col) =
                    __floats2bfloat162_rn(acc[mt][nt][0], acc[mt][nt][1]);
                *(__nv_bfloat162*)(sG + (ra + 8) * LDH + col) =
                    __floats2bfloat162_rn(acc[mt][nt][2], acc[mt][nt][3]);
            }
    }
    __syncthreads();

    // ---------------- out = T @ W9 + b9 + x ----------------
    gemm_w(g_W9, sG, LDH, sW0, sW1, acc, tid, lane, r0, nb);
    #pragma unroll
    for (int mt = 0; mt < 4; mt++)
        #pragma unroll
        for (int nt = 0; nt < 8; nt++) {
            int col = nb + nt * 8 + tig * 2;
            float b0v = sBias[col], b1v = sBias[col + 1];
            int ra = r0 + mt * 16 + grp, rb = ra + 8;
            float2 xa = *(const float2*)(xrow + ra * CH + col);
            float2 xb = *(const float2*)(xrow + rb * CH + col);
            *(float2*)(orow + ra * CH + col) =
                make_float2(acc[mt][nt][0] + b0v + xa.x, acc[mt][nt][1] + b1v + xa.y);
            *(float2*)(orow + rb * CH + col) =
                make_float2(acc[mt][nt][2] + b0v + xb.x, acc[mt][nt][3] + b1v + xb.y);
        }
}

extern "C" void kernel_launch(void* const* d_in, const int* in_sizes, int n_in,
                              void* d_out, int out_size) {
    const float* x  = (const float*)d_in[0];
    const float* Wq = (const float*)d_in[1];
    const float* bq = (const float*)d_in[2];
    const float* Wk = (const float*)d_in[3];
    const float* bk = (const float*)d_in[4];
    const float* Wv = (const float*)d_in[5];
    const float* bv = (const float*)d_in[6];
    const float* Wo = (const float*)d_in[7];
    const float* bo = (const float*)d_in[8];
    float* out = (float*)d_out;

    dim3 g8(8, 8, 2);
    setup_gemm_kernel<<<g8, 256>>>(Wq, Wk, Wv, Wo);
    setup_vec_kernel<<<1, 256>>>(Wk, Wo, bq, bk, bv, bo);

    cudaFuncSetAttribute(attn_kernel, cudaFuncAttributeMaxDynamicSharedMemorySize, SMEM_BYTES);
    attn_kernel<<<1024, 256, SMEM_BYTES>>>(x, out);
}

// round 9
// speedup vs baseline: 1.1229x; 1.1229x over previous
#include <cuda_runtime.h>
#include <cuda_bf16.h>
#include <cstdint>

// AttentionBlock fused kernel, sm_103a. Round 8:
// R4 structure (M=64/CTA, 32x64 warp tiles, 2 CTAs/SM) but weights stored in
// per-lane MMA fragment order -> B operands come straight from L2 via
// coalesced LDG.64. No W smem staging, no cp.async, 4 barriers/CTA total.

#define CH    256
#define LDH   264   // bf16 tile row stride in halves
#define LDP   72    // bf16 P tile stride

// Fused weights in fragment order: uint2 per lane per (n8, k16) tile.
// idx_uint2 = (n8*16 + k16)*32 + lane;  v.x = {B[k0+2t][n], B[k0+2t+1][n]}, v.y = k+8 pair.
__device__ uint2 g_M8f[32 * 16 * 32];   // Wq @ Wk^T  (k = a-dim, n = b-dim)
__device__ uint2 g_W9f[32 * 16 * 32];   // Wv @ Wo
__device__ float g_b9[CH];              // bv @ Wo + bo
__device__ float g_w8[CH];              // Wk @ bq
__device__ float g_s8;                  // bk . bq

// ---- setup: fused weight products scattered into fragment order ----
__global__ void setup_gemm_kernel(const float* __restrict__ Wq, const float* __restrict__ Wk,
                                  const float* __restrict__ Wv, const float* __restrict__ Wo) {
    __shared__ float As[32][33];
    __shared__ float Bs[32][33];
    const int tid = threadIdx.x;
    const int tx = tid & 31, ty = tid >> 5;
    const int a0 = blockIdx.y * 32, b0 = blockIdx.x * 32;
    const int z = blockIdx.z;
    const float* A = z ? Wv : Wq;

    float acc[4] = {0.f, 0.f, 0.f, 0.f};
    for (int d0 = 0; d0 < CH; d0 += 32) {
        {
            int i = tid >> 3, j = (tid & 7) * 4;
            float4 v = *(const float4*)(A + (a0 + i) * CH + d0 + j);
            As[i][j] = v.x; As[i][j + 1] = v.y; As[i][j + 2] = v.z; As[i][j + 3] = v.w;
        }
        if (z == 0) {   // Bs[dd][c] = Wk[b0+c][d0+dd]
            int i = tid >> 3, j = (tid & 7) * 4;
            float4 v = *(const float4*)(Wk + (b0 + i) * CH + d0 + j);
            Bs[j][i] = v.x; Bs[j + 1][i] = v.y; Bs[j + 2][i] = v.z; Bs[j + 3][i] = v.w;
        } else {        // Bs[dd][c] = Wo[d0+dd][b0+c]
            int j = tid >> 3, i = (tid & 7) * 4;
            float4 v = *(const float4*)(Wo + (d0 + j) * CH + b0 + i);
            Bs[j][i] = v.x; Bs[j][i + 1] = v.y; Bs[j][i + 2] = v.z; Bs[j][i + 3] = v.w;
        }
        __syncthreads();
        #pragma unroll
        for (int dd = 0; dd < 32; dd++) {
            float b = Bs[dd][tx];
            #pragma unroll
            for (int r = 0; r < 4; r++) acc[r] += As[ty + 8 * r][dd] * b;
        }
        __syncthreads();
    }
    __nv_bfloat16* dst = (__nv_bfloat16*)(z ? g_W9f : g_M8f);
    #pragma unroll
    for (int r = 0; r < 4; r++) {
        int a = a0 + ty + 8 * r;          // k-dim
        int b = b0 + tx;                  // n-dim
        int idx = ((((b >> 3) * 16 + (a >> 4)) * 32) + (b & 7) * 4 + ((a & 7) >> 1)) * 4
                + ((a >> 3) & 1) * 2 + (a & 1);
        dst[idx] = __float2bfloat16(acc[r]);
    }
}

__global__ void setup_vec_kernel(const float* __restrict__ Wk, const float* __restrict__ Wo,
                                 const float* __restrict__ bq, const float* __restrict__ bk,
                                 const float* __restrict__ bv, const float* __restrict__ bo) {
    int c = threadIdx.x;
    float w8 = 0.f, b9 = 0.f;
    for (int d = 0; d < CH; d++) {
        w8 += Wk[c * CH + d] * bq[d];
        b9 += bv[d] * Wo[d * CH + c];
    }
    g_w8[c] = w8;
    g_b9[c] = b9 + bo[c];
    if (c == 0) {
        float s = 0.f;
        for (int d = 0; d < CH; d++) s += bk[d] * bq[d];
        g_s8 = s;
    }
}

// ---- mma.sync helpers ----
__device__ __forceinline__ uint32_t smem_u32(const void* p) {
    return (uint32_t)__cvta_generic_to_shared(p);
}
__device__ __forceinline__ void ldm_x4(uint32_t addr, uint32_t& a0, uint32_t& a1,
                                       uint32_t& a2, uint32_t& a3) {
    asm volatile("ldmatrix.sync.aligned.m8n8.x4.shared.b16 {%0,%1,%2,%3}, [%4];"
                 : "=r"(a0), "=r"(a1), "=r"(a2), "=r"(a3) : "r"(addr));
}
__device__ __forceinline__ void ldm_x4t(uint32_t addr, uint32_t& b0, uint32_t& b1,
                                        uint32_t& b2, uint32_t& b3) {
    asm volatile("ldmatrix.sync.aligned.m8n8.x4.trans.shared.b16 {%0,%1,%2,%3}, [%4];"
                 : "=r"(b0), "=r"(b1), "=r"(b2), "=r"(b3) : "r"(addr));
}
__device__ __forceinline__ void mma_bf16(float c[4],
                                         uint32_t a0, uint32_t a1, uint32_t a2, uint32_t a3,
                                         uint32_t b0, uint32_t b1) {
    asm volatile("mma.sync.aligned.m16n8k16.row.col.f32.bf16.bf16.f32 "
                 "{%0,%1,%2,%3}, {%4,%5,%6,%7}, {%8,%9}, {%0,%1,%2,%3};"
                 : "+f"(c[0]), "+f"(c[1]), "+f"(c[2]), "+f"(c[3])
                 : "r"(a0), "r"(a1), "r"(a2), "r"(a3), "r"(b0), "r"(b1));
}

// GEMM, B from L2 fragments: acc[32x64] = A[64x256](smem) @ W(frag gmem).
__device__ __forceinline__ void gemm_f(const uint2* __restrict__ Wf,
                                       const __nv_bfloat16* sA,
                                       float acc[2][8][4],
                                       int lane, int r0, int nb) {
    #pragma unroll
    for (int mt = 0; mt < 2; mt++)
        #pragma unroll
        for (int nt = 0; nt < 8; nt++)
            acc[mt][nt][0] = acc[mt][nt][1] = acc[mt][nt][2] = acc[mt][nt][3] = 0.f;

    const uint2* wb = Wf + ((nb >> 3) * 16) * 32 + lane;
    #pragma unroll
    for (int ks = 0; ks < 16; ks++) {
        uint2 v[8];
        #pragma unroll
        for (int nt = 0; nt < 8; nt++) v[nt] = wb[(nt * 16 + ks) * 32];
        uint32_t a[2][4];
        #pragma unroll
        for (int mt = 0; mt < 2; mt++)
            ldm_x4(smem_u32(sA + (r0 + mt * 16 + (lane & 15)) * LDH
                            + ks * 16 + ((lane >> 4) << 3)),
                   a[mt][0], a[mt][1], a[mt][2], a[mt][3]);
        #pragma unroll
        for (int nt = 0; nt < 8; nt++) {
            mma_bf16(acc[0][nt], a[0][0], a[0][1], a[0][2], a[0][3], v[nt].x, v[nt].y);
            mma_bf16(acc[1][nt], a[1][0], a[1][1], a[1][2], a[1][3], v[nt].x, v[nt].y);
        }
    }
}

// SMEM: sX 33792 + sG 33792 + sP 9216 + sC 256 + sBias 1024 = 78080
#define SMEM_BYTES 78080

__global__ void __launch_bounds__(256, 2)
attn_kernel(const float* __restrict__ x, float* __restrict__ out)
{
    extern __shared__ char smem_raw[];
    __nv_bfloat16* sX  = (__nv_bfloat16*)smem_raw;           // [64][LDH]
    __nv_bfloat16* sG  = sX + 64 * LDH;                      // [64][LDH]
    __nv_bfloat16* sP  = sG + 64 * LDH;                      // [64][LDP]
    float*         sC  = (float*)(sP + 64 * LDP);            // [64]
    float*      sBias  = sC + 64;                            // [256]

    const int tid  = threadIdx.x;
    const int wid  = tid >> 5;
    const int lane = tid & 31;
    const int grp  = lane >> 2;
    const int tig  = lane & 3;

    const size_t base = (size_t)blockIdx.x * 64 * CH;
    const float* xrow = x   + base;
    float*       orow = out + base;

    // ---------------- Phase 0: bias + x tile (fp32 -> bf16) + c_j ----------------
    sBias[tid] = g_b9[tid];
    {
        const float4* xv = (const float4*)xrow;
        #pragma unroll
        for (int t = 0; t < 16; t++) {
            int i = tid + t * 256;             // 4096 float4
            int row = i >> 6;
            int colf = (i & 63) * 4;
            float4 v = xv[i];
            __nv_bfloat162* d = (__nv_bfloat162*)(sX + row * LDH + colf);
            d[0] = __floats2bfloat162_rn(v.x, v.y);
            d[1] = __floats2bfloat162_rn(v.z, v.w);
        }
    }
    // c_j = x_j . w8 + s8  (4 threads per row)
    {
        int row = tid >> 2, q = tid & 3;
        const float4* xv = (const float4*)(xrow + row * CH + q * 64);
        float s = 0.f;
        #pragma unroll
        for (int j = 0; j < 16; j++) {
            float4 v = xv[j];
            int c = q * 64 + j * 4;
            s += v.x * g_w8[c] + v.y * g_w8[c + 1] + v.z * g_w8[c + 2] + v.w * g_w8[c + 3];
        }
        s += __shfl_xor_sync(0xffffffffu, s, 1);
        s += __shfl_xor_sync(0xffffffffu, s, 2);
        if (q == 0) sC[row] = s + g_s8;
    }
    __syncthreads();

    const int r0 = (wid >> 2) * 32;   // warp's 32 rows
    const int nb = (wid & 3) * 64;    // warp's 64 cols

    float acc[2][8][4];

    // ---------------- G = X @ M8 -> sG ----------------
    gemm_f(g_M8f, sX, acc, lane, r0, nb);
    #pragma unroll
    for (int mt = 0; mt < 2; mt++)
        #pragma unroll
        for (int nt = 0; nt < 8; nt++) {
            int col = nb + nt * 8 + tig * 2;
            int ra = r0 + mt * 16 + grp;
            *(__nv_bfloat162*)(sG + ra * LDH + col) =
                __floats2bfloat162_rn(acc[mt][nt][0], acc[mt][nt][1]);
            *(__nv_bfloat162*)(sG + (ra + 8) * LDH + col) =
                __floats2bfloat162_rn(acc[mt][nt][2], acc[mt][nt][3]);
        }
    __syncthreads();

    // ---------------- S = (G X^T + c_j)*scale, softmax -> P (warps 0-3) ----
    if (wid < 4) {
        const int r0s = wid * 16;     // 16 rows, all 64 cols
        float sa[8][4];
        #pragma unroll
        for (int nt = 0; nt < 8; nt++)
            sa[nt][0] = sa[nt][1] = sa[nt][2] = sa[nt][3] = 0.f;
        #pragma unroll
        for (int ks = 0; ks < 16; ks++) {
            uint32_t a0, a1, a2, a3;
            ldm_x4(smem_u32(sG + (r0s + (lane & 15)) * LDH + ks * 16 + ((lane >> 4) << 3)),
                   a0, a1, a2, a3);
            #pragma unroll
            for (int nt16 = 0; nt16 < 2; nt16++) {
                uint32_t b0, b1, b2, b3;
                ldm_x4(smem_u32(sX + (nt16 * 32 + ((lane >> 4) << 3) + (lane & 7)) * LDH
                                + ks * 16 + (((lane >> 3) & 1) << 3)),
                       b0, b1, b2, b3);
                mma_bf16(sa[4 * nt16],     a0, a1, a2, a3, b0, b1);
                mma_bf16(sa[4 * nt16 + 1], a0, a1, a2, a3, b2, b3);
                uint32_t c0, c1, c2, c3;
                ldm_x4(smem_u32(sX + (nt16 * 32 + 16 + ((lane >> 4) << 3) + (lane & 7)) * LDH
                                + ks * 16 + (((lane >> 3) & 1) << 3)),
                       c0, c1, c2, c3);
                mma_bf16(sa[4 * nt16 + 2], a0, a1, a2, a3, c0, c1);
                mma_bf16(sa[4 * nt16 + 3], a0, a1, a2, a3, c2, c3);
            }
        }
        const float SCALE = 1.0f / (256.0f * 16.0f * 0.70710678118654752f);
        float v0[16], v1[16];
        #pragma unroll
        for (int nt = 0; nt < 8; nt++) {
            int col = nt * 8 + tig * 2;
            float c0 = sC[col], c1 = sC[col + 1];
            v0[2 * nt] = (sa[nt][0] + c0) * SCALE; v0[2 * nt + 1] = (sa[nt][1] + c1) * SCALE;
            v1[2 * nt] = (sa[nt][2] + c0) * SCALE; v1[2 * nt + 1] = (sa[nt][3] + c1) * SCALE;
        }
        float m0 = v0[0], m1 = v1[0];
        #pragma unroll
        for (int i = 1; i < 16; i++) { m0 = fmaxf(m0, v0[i]); m1 = fmaxf(m1, v1[i]); }
        m0 = fmaxf(m0, __shfl_xor_sync(0xffffffffu, m0, 1));
        m0 = fmaxf(m0, __shfl_xor_sync(0xffffffffu, m0, 2));
        m1 = fmaxf(m1, __shfl_xor_sync(0xffffffffu, m1, 1));
        m1 = fmaxf(m1, __shfl_xor_sync(0xffffffffu, m1, 2));
        float s0 = 0.f, s1 = 0.f;
        #pragma unroll
        for (int i = 0; i < 16; i++) {
            v0[i] = __expf(v0[i] - m0); s0 += v0[i];
            v1[i] = __expf(v1[i] - m1); s1 += v1[i];
        }
        s0 += __shfl_xor_sync(0xffffffffu, s0, 1);
        s0 += __shfl_xor_sync(0xffffffffu, s0, 2);
        s1 += __shfl_xor_sync(0xffffffffu, s1, 1);
        s1 += __shfl_xor_sync(0xffffffffu, s1, 2);
        float i0 = 1.0f / s0, i1 = 1.0f / s1;
        int ra = r0s + grp, rb = ra + 8;
        #pragma unroll
        for (int nt = 0; nt < 8; nt++) {
            *(__nv_bfloat162*)(sP + ra * LDP + nt * 8 + tig * 2) =
                __floats2bfloat162_rn(v0[2 * nt] * i0, v0[2 * nt + 1] * i0);
            *(__nv_bfloat162*)(sP + rb * LDP + nt * 8 + tig * 2) =
                __floats2bfloat162_rn(v1[2 * nt] * i1, v1[2 * nt + 1] * i1);
        }
    }
    __syncthreads();

    // ---------------- T = P @ X -> sG (G dead after S) ----------------
    {
        #pragma unroll
        for (int mt = 0; mt < 2; mt++)
            #pragma unroll
            for (int nt = 0; nt < 8; nt++)
                acc[mt][nt][0] = acc[mt][nt][1] = acc[mt][nt][2] = acc[mt][nt][3] = 0.f;
        #pragma unroll
        for (int ks = 0; ks < 4; ks++) {
            uint32_t a[2][4];
            #pragma unroll
            for (int mt = 0; mt < 2; mt++)
                ldm_x4(smem_u32(sP + (r0 + mt * 16 + (lane & 15)) * LDP
                                + ks * 16 + ((lane >> 4) << 3)),
                       a[mt][0], a[mt][1], a[mt][2], a[mt][3]);
            #pragma unroll
            for (int nt16 = 0; nt16 < 4; nt16++) {
                uint32_t b0, b1, b2, b3;
                ldm_x4t(smem_u32(sX + (ks * 16 + (lane & 15)) * LDH
                                 + nb + nt16 * 16 + ((lane >> 4) << 3)),
                        b0, b1, b2, b3);
                #pragma unroll
                for (int mt = 0; mt < 2; mt++) {
                    mma_bf16(acc[mt][2 * nt16],     a[mt][0], a[mt][1], a[mt][2], a[mt][3], b0, b1);
                    mma_bf16(acc[mt][2 * nt16 + 1], a[mt][0], a[mt][1], a[mt][2], a[mt][3], b2, b3);
                }
            }
        }
        __syncthreads();   // all S-phase reads of sG complete before overwrite
        #pragma unroll
        for (int mt = 0; mt < 2; mt++)
            #pragma unroll
            for (int nt = 0; nt < 8; nt++) {
                int col = nb + nt * 8 + tig * 2;
                int ra = r0 + mt * 16 + grp;
                *(__nv_bfloat162*)(sG + ra * LDH + col) =
                    __floats2bfloat162_rn(acc[mt][nt][0], acc[mt][nt][1]);
                *(__nv_bfloat162*)(sG + (ra + 8) * LDH + col) =
                    __floats2bfloat162_rn(acc[mt][nt][2], acc[mt][nt][3]);
            }
    }
    __syncthreads();

    // ---------------- out = T @ W9 + b9 + x ----------------
    gemm_f(g_W9f, sG, acc, lane, r0, nb);
    #pragma unroll
    for (int mt = 0; mt < 2; mt++)
        #pragma unroll
        for (int nt = 0; nt < 8; nt++) {
            int col = nb + nt * 8 + tig * 2;
            float b0v = sBias[col], b1v = sBias[col + 1];
            int ra = r0 + mt * 16 + grp, rb = ra + 8;
            float2 xa = *(const float2*)(xrow + ra * CH + col);
            float2 xb = *(const float2*)(xrow + rb * CH + col);
            *(float2*)(orow + ra * CH + col) =
                make_float2(acc[mt][nt][0] + b0v + xa.x, acc[mt][nt][1] + b1v + xa.y);
            *(float2*)(orow + rb * CH + col) =
                make_float2(acc[mt][nt][2] + b0v + xb.x, acc[mt][nt][3] + b1v + xb.y);
        }
}

extern "C" void kernel_launch(void* const* d_in, const int* in_sizes, int n_in,
                              void* d_out, int out_size) {
    const float* x  = (const float*)d_in[0];
    const float* Wq = (const float*)d_in[1];
    const float* bq = (const float*)d_in[2];
    const float* Wk = (const float*)d_in[3];
    const float* bk = (const float*)d_in[4];
    const float* Wv = (const float*)d_in[5];
    const float* bv = (const float*)d_in[6];
    const float* Wo = (const float*)d_in[7];
    const float* bo = (const float*)d_in[8];
    float* out = (float*)d_out;

    dim3 g8(8, 8, 2);
    setup_gemm_kernel<<<g8, 256>>>(Wq, Wk, Wv, Wo);
    setup_vec_kernel<<<1, 256>>>(Wk, Wo, bq, bk, bv, bo);

    cudaFuncSetAttribute(attn_kernel, cudaFuncAttributeMaxDynamicSharedMemorySize, SMEM_BYTES);
    attn_kernel<<<2048, 256, SMEM_BYTES>>>(x, out);
}

// round 10
// speedup vs baseline: 1.2221x; 1.0883x over previous
#include <cuda_runtime.h>
#include <cuda_bf16.h>
#include <cstdint>

// AttentionBlock fused kernel, sm_103a. Round 9:
// R8 (fragment-order weights from L2, M=64/CTA, 32x64 tiles, 2 CTAs/SM)
// + software-pipelined W-fragment prefetch in gemm_f
// + setup_vec folded into setup_gemm (one setup launch).

#define CH    256
#define LDH   264   // bf16 tile row stride in halves
#define LDP   72    // bf16 P tile stride

// Fused weights in fragment order: uint2 per lane per (n8, k16) tile.
// idx_uint2 = (n8*16 + k16)*32 + lane;  v.x = {B[k0+2t][n], B[k0+2t+1][n]}, v.y = k+8 pair.
__device__ uint2 g_M8f[32 * 16 * 32];   // Wq @ Wk^T  (k = a-dim, n = b-dim)
__device__ uint2 g_W9f[32 * 16 * 32];   // Wv @ Wo
__device__ float g_b9[CH];              // bv @ Wo + bo
__device__ float g_w8[CH];              // Wk @ bq
__device__ float g_s8;                  // bk . bq

// ---- setup: fused weight products scattered into fragment order (+vec on z==2) ----
__global__ void setup_gemm_kernel(const float* __restrict__ Wq, const float* __restrict__ Wk,
                                  const float* __restrict__ Wv, const float* __restrict__ Wo,
                                  const float* __restrict__ bq, const float* __restrict__ bk,
                                  const float* __restrict__ bv, const float* __restrict__ bo) {
    const int z = blockIdx.z;
    if (z == 2) {
        if (blockIdx.x == 0 && blockIdx.y == 0) {
            int c = threadIdx.x;
            float w8 = 0.f, b9 = 0.f;
            for (int d = 0; d < CH; d++) {
                w8 += Wk[c * CH + d] * bq[d];
                b9 += bv[d] * Wo[d * CH + c];
            }
            g_w8[c] = w8;
            g_b9[c] = b9 + bo[c];
            if (c == 0) {
                float s = 0.f;
                for (int d = 0; d < CH; d++) s += bk[d] * bq[d];
                g_s8 = s;
            }
        }
        return;
    }
    __shared__ float As[32][33];
    __shared__ float Bs[32][33];
    const int tid = threadIdx.x;
    const int tx = tid & 31, ty = tid >> 5;
    const int a0 = blockIdx.y * 32, b0 = blockIdx.x * 32;
    const float* A = z ? Wv : Wq;

    float acc[4] = {0.f, 0.f, 0.f, 0.f};
    for (int d0 = 0; d0 < CH; d0 += 32) {
        {
            int i = tid >> 3, j = (tid & 7) * 4;
            float4 v = *(const float4*)(A + (a0 + i) * CH + d0 + j);
            As[i][j] = v.x; As[i][j + 1] = v.y; As[i][j + 2] = v.z; As[i][j + 3] = v.w;
        }
        if (z == 0) {   // Bs[dd][c] = Wk[b0+c][d0+dd]
            int i = tid >> 3, j = (tid & 7) * 4;
            float4 v = *(const float4*)(Wk + (b0 + i) * CH + d0 + j);
            Bs[j][i] = v.x; Bs[j + 1][i] = v.y; Bs[j + 2][i] = v.z; Bs[j + 3][i] = v.w;
        } else {        // Bs[dd][c] = Wo[d0+dd][b0+c]
            int j = tid >> 3, i = (tid & 7) * 4;
            float4 v = *(const float4*)(Wo + (d0 + j) * CH + b0 + i);
            Bs[j][i] = v.x; Bs[j][i + 1] = v.y; Bs[j][i + 2] = v.z; Bs[j][i + 3] = v.w;
        }
        __syncthreads();
        #pragma unroll
        for (int dd = 0; dd < 32; dd++) {
            float b = Bs[dd][tx];
            #pragma unroll
            for (int r = 0; r < 4; r++) acc[r] += As[ty + 8 * r][dd] * b;
        }
        __syncthreads();
    }
    __nv_bfloat16* dst = (__nv_bfloat16*)(z ? g_W9f : g_M8f);
    #pragma unroll
    for (int r = 0; r < 4; r++) {
        int a = a0 + ty + 8 * r;          // k-dim
        int b = b0 + tx;                  // n-dim
        int idx = ((((b >> 3) * 16 + (a >> 4)) * 32) + (b & 7) * 4 + ((a & 7) >> 1)) * 4
                + ((a >> 3) & 1) * 2 + (a & 1);
        dst[idx] = __float2bfloat16(acc[r]);
    }
}

// ---- mma.sync helpers ----
__device__ __forceinline__ uint32_t smem_u32(const void* p) {
    return (uint32_t)__cvta_generic_to_shared(p);
}
__device__ __forceinline__ void ldm_x4(uint32_t addr, uint32_t& a0, uint32_t& a1,
                                       uint32_t& a2, uint32_t& a3) {
    asm volatile("ldmatrix.sync.aligned.m8n8.x4.shared.b16 {%0,%1,%2,%3}, [%4];"
                 : "=r"(a0), "=r"(a1), "=r"(a2), "=r"(a3) : "r"(addr));
}
__device__ __forceinline__ void ldm_x4t(uint32_t addr, uint32_t& b0, uint32_t& b1,
                                        uint32_t& b2, uint32_t& b3) {
    asm volatile("ldmatrix.sync.aligned.m8n8.x4.trans.shared.b16 {%0,%1,%2,%3}, [%4];"
                 : "=r"(b0), "=r"(b1), "=r"(b2), "=r"(b3) : "r"(addr));
}
__device__ __forceinline__ void mma_bf16(float c[4],
                                         uint32_t a0, uint32_t a1, uint32_t a2, uint32_t a3,
                                         uint32_t b0, uint32_t b1) {
    asm volatile("mma.sync.aligned.m16n8k16.row.col.f32.bf16.bf16.f32 "
                 "{%0,%1,%2,%3}, {%4,%5,%6,%7}, {%8,%9}, {%0,%1,%2,%3};"
                 : "+f"(c[0]), "+f"(c[1]), "+f"(c[2]), "+f"(c[3])
                 : "r"(a0), "r"(a1), "r"(a2), "r"(a3), "r"(b0), "r"(b1));
}

// GEMM, B from L2 fragments with next-step prefetch:
// acc[32x64] = A[64x256](smem) @ W(frag gmem).
__device__ __forceinline__ void gemm_f(const uint2* __restrict__ Wf,
                                       const __nv_bfloat16* sA,
                                       float acc[2][8][4],
                                       int lane, int r0, int nb) {
    #pragma unroll
    for (int mt = 0; mt < 2; mt++)
        #pragma unroll
        for (int nt = 0; nt < 8; nt++)
            acc[mt][nt][0] = acc[mt][nt][1] = acc[mt][nt][2] = acc[mt][nt][3] = 0.f;

    const uint2* wb = Wf + ((nb >> 3) * 16) * 32 + lane;
    uint2 vc[8], vn[8];
    #pragma unroll
    for (int nt = 0; nt < 8; nt++) vc[nt] = wb[(nt * 16) * 32];

    #pragma unroll
    for (int ks = 0; ks < 16; ks++) {
        if (ks < 15) {
            #pragma unroll
            for (int nt = 0; nt < 8; nt++) vn[nt] = wb[(nt * 16 + ks + 1) * 32];
        }
        uint32_t a[2][4];
        #pragma unroll
        for (int mt = 0; mt < 2; mt++)
            ldm_x4(smem_u32(sA + (r0 + mt * 16 + (lane & 15)) * LDH
                            + ks * 16 + ((lane >> 4) << 3)),
                   a[mt][0], a[mt][1], a[mt][2], a[mt][3]);
        #pragma unroll
        for (int nt = 0; nt < 8; nt++) {
            mma_bf16(acc[0][nt], a[0][0], a[0][1], a[0][2], a[0][3], vc[nt].x, vc[nt].y);
            mma_bf16(acc[1][nt], a[1][0], a[1][1], a[1][2], a[1][3], vc[nt].x, vc[nt].y);
        }
        if (ks < 15) {
            #pragma unroll
            for (int nt = 0; nt < 8; nt++) vc[nt] = vn[nt];
        }
    }
}

// SMEM: sX 33792 + sG 33792 + sP 9216 + sC 256 + sBias 1024 = 78080
#define SMEM_BYTES 78080

__global__ void __launch_bounds__(256, 2)
attn_kernel(const float* __restrict__ x, float* __restrict__ out)
{
    extern __shared__ char smem_raw[];
    __nv_bfloat16* sX  = (__nv_bfloat16*)smem_raw;           // [64][LDH]
    __nv_bfloat16* sG  = sX + 64 * LDH;                      // [64][LDH]
    __nv_bfloat16* sP  = sG + 64 * LDH;                      // [64][LDP]
    float*         sC  = (float*)(sP + 64 * LDP);            // [64]
    float*      sBias  = sC + 64;                            // [256]

    const int tid  = threadIdx.x;
    const int wid  = tid >> 5;
    const int lane = tid & 31;
    const int grp  = lane >> 2;
    const int tig  = lane & 3;

    const size_t base = (size_t)blockIdx.x * 64 * CH;
    const float* xrow = x   + base;
    float*       orow = out + base;

    // ---------------- Phase 0: bias + x tile (fp32 -> bf16) + c_j ----------------
    sBias[tid] = g_b9[tid];
    {
        const float4* xv = (const float4*)xrow;
        #pragma unroll
        for (int t = 0; t < 16; t++) {
            int i = tid + t * 256;             // 4096 float4
            int row = i >> 6;
            int colf = (i & 63) * 4;
            float4 v = xv[i];
            __nv_bfloat162* d = (__nv_bfloat162*)(sX + row * LDH + colf);
            d[0] = __floats2bfloat162_rn(v.x, v.y);
            d[1] = __floats2bfloat162_rn(v.z, v.w);
        }
    }
    // c_j = x_j . w8 + s8  (4 threads per row)
    {
        int row = tid >> 2, q = tid & 3;
        const float4* xv = (const float4*)(xrow + row * CH + q * 64);
        float s = 0.f;
        #pragma unroll
        for (int j = 0; j < 16; j++) {
            float4 v = xv[j];
            int c = q * 64 + j * 4;
            s += v.x * g_w8[c] + v.y * g_w8[c + 1] + v.z * g_w8[c + 2] + v.w * g_w8[c + 3];
        }
        s += __shfl_xor_sync(0xffffffffu, s, 1);
        s += __shfl_xor_sync(0xffffffffu, s, 2);
        if (q == 0) sC[row] = s + g_s8;
    }
    __syncthreads();

    const int r0 = (wid >> 2) * 32;   // warp's 32 rows
    const int nb = (wid & 3) * 64;    // warp's 64 cols

    float acc[2][8][4];

    // ---------------- G = X @ M8 -> sG ----------------
    gemm_f(g_M8f, sX, acc, lane, r0, nb);
    #pragma unroll
    for (int mt = 0; mt < 2; mt++)
        #pragma unroll
        for (int nt = 0; nt < 8; nt++) {
            int col = nb + nt * 8 + tig * 2;
            int ra = r0 + mt * 16 + grp;
            *(__nv_bfloat162*)(sG + ra * LDH + col) =
                __floats2bfloat162_rn(acc[mt][nt][0], acc[mt][nt][1]);
            *(__nv_bfloat162*)(sG + (ra + 8) * LDH + col) =
                __floats2bfloat162_rn(acc[mt][nt][2], acc[mt][nt][3]);
        }
    __syncthreads();

    // ---------------- S = (G X^T + c_j)*scale, softmax -> P (warps 0-3) ----
    if (wid < 4) {
        const int r0s = wid * 16;     // 16 rows, all 64 cols
        float sa[8][4];
        #pragma unroll
        for (int nt = 0; nt < 8; nt++)
            sa[nt][0] = sa[nt][1] = sa[nt][2] = sa[nt][3] = 0.f;
        #pragma unroll
        for (int ks = 0; ks < 16; ks++) {
            uint32_t a0, a1, a2, a3;
            ldm_x4(smem_u32(sG + (r0s + (lane & 15)) * LDH + ks * 16 + ((lane >> 4) << 3)),
                   a0, a1, a2, a3);
            #pragma unroll
            for (int nt16 = 0; nt16 < 2; nt16++) {
                uint32_t b0, b1, b2, b3;
                ldm_x4(smem_u32(sX + (nt16 * 32 + ((lane >> 4) << 3) + (lane & 7)) * LDH
                                + ks * 16 + (((lane >> 3) & 1) << 3)),
                       b0, b1, b2, b3);
                mma_bf16(sa[4 * nt16],     a0, a1, a2, a3, b0, b1);
                mma_bf16(sa[4 * nt16 + 1], a0, a1, a2, a3, b2, b3);
                uint32_t c0, c1, c2, c3;
                ldm_x4(smem_u32(sX + (nt16 * 32 + 16 + ((lane >> 4) << 3) + (lane & 7)) * LDH
                                + ks * 16 + (((lane >> 3) & 1) << 3)),
                       c0, c1, c2, c3);
                mma_bf16(sa[4 * nt16 + 2], a0, a1, a2, a3, c0, c1);
                mma_bf16(sa[4 * nt16 + 3], a0, a1, a2, a3, c2, c3);
            }
        }
        const float SCALE = 1.0f / (256.0f * 16.0f * 0.70710678118654752f);
        float v0[16], v1[16];
        #pragma unroll
        for (int nt = 0; nt < 8; nt++) {
            int col = nt * 8 + tig * 2;
            float c0 = sC[col], c1 = sC[col + 1];
            v0[2 * nt] = (sa[nt][0] + c0) * SCALE; v0[2 * nt + 1] = (sa[nt][1] + c1) * SCALE;
            v1[2 * nt] = (sa[nt][2] + c0) * SCALE; v1[2 * nt + 1] = (sa[nt][3] + c1) * SCALE;
        }
        float m0 = v0[0], m1 = v1[0];
        #pragma unroll
        for (int i = 1; i < 16; i++) { m0 = fmaxf(m0, v0[i]); m1 = fmaxf(m1, v1[i]); }
        m0 = fmaxf(m0, __shfl_xor_sync(0xffffffffu, m0, 1));
        m0 = fmaxf(m0, __shfl_xor_sync(0xffffffffu, m0, 2));
        m1 = fmaxf(m1, __shfl_xor_sync(0xffffffffu, m1, 1));
        m1 = fmaxf(m1, __shfl_xor_sync(0xffffffffu, m1, 2));
        float s0 = 0.f, s1 = 0.f;
        #pragma unroll
        for (int i = 0; i < 16; i++) {
            v0[i] = __expf(v0[i] - m0); s0 += v0[i];
            v1[i] = __expf(v1[i] - m1); s1 += v1[i];
        }
        s0 += __shfl_xor_sync(0xffffffffu, s0, 1);
        s0 += __shfl_xor_sync(0xffffffffu, s0, 2);
        s1 += __shfl_xor_sync(0xffffffffu, s1, 1);
        s1 += __shfl_xor_sync(0xffffffffu, s1, 2);
        float i0 = 1.0f / s0, i1 = 1.0f / s1;
        int ra = r0s + grp, rb = ra + 8;
        #pragma unroll
        for (int nt = 0; nt < 8; nt++) {
            *(__nv_bfloat162*)(sP + ra * LDP + nt * 8 + tig * 2) =
                __floats2bfloat162_rn(v0[2 * nt] * i0, v0[2 * nt + 1] * i0);
            *(__nv_bfloat162*)(sP + rb * LDP + nt * 8 + tig * 2) =
                __floats2bfloat162_rn(v1[2 * nt] * i1, v1[2 * nt + 1] * i1);
        }
    }
    __syncthreads();

    // ---------------- T = P @ X -> sG (G dead after S) ----------------
    {
        #pragma unroll
        for (int mt = 0; mt < 2; mt++)
            #pragma unroll
            for (int nt = 0; nt < 8; nt++)
                acc[mt][nt][0] = acc[mt][nt][1] = acc[mt][nt][2] = acc[mt][nt][3] = 0.f;
        #pragma unroll
        for (int ks = 0; ks < 4; ks++) {
            uint32_t a[2][4];
            #pragma unroll
            for (int mt = 0; mt < 2; mt++)
                ldm_x4(smem_u32(sP + (r0 + mt * 16 + (lane & 15)) * LDP
                                + ks * 16 + ((lane >> 4) << 3)),
                       a[mt][0], a[mt][1], a[mt][2], a[mt][3]);
            #pragma unroll
            for (int nt16 = 0; nt16 < 4; nt16++) {
                uint32_t b0, b1, b2, b3;
                ldm_x4t(smem_u32(sX + (ks * 16 + (lane & 15)) * LDH
                                 + nb + nt16 * 16 + ((lane >> 4) << 3)),
                        b0, b1, b2, b3);
                #pragma unroll
                for (int mt = 0; mt < 2; mt++) {
                    mma_bf16(acc[mt][2 * nt16],     a[mt][0], a[mt][1], a[mt][2], a[mt][3], b0, b1);
                    mma_bf16(acc[mt][2 * nt16 + 1], a[mt][0], a[mt][1], a[mt][2], a[mt][3], b2, b3);
                }
            }
        }
        __syncthreads();   // all S-phase reads of sG complete before overwrite
        #pragma unroll
        for (int mt = 0; mt < 2; mt++)
            #pragma unroll
            for (int nt = 0; nt < 8; nt++) {
                int col = nb + nt * 8 + tig * 2;
                int ra = r0 + mt * 16 + grp;
                *(__nv_bfloat162*)(sG + ra * LDH + col) =
                    __floats2bfloat162_rn(acc[mt][nt][0], acc[mt][nt][1]);
                *(__nv_bfloat162*)(sG + (ra + 8) * LDH + col) =
                    __floats2bfloat162_rn(acc[mt][nt][2], acc[mt][nt][3]);
            }
    }
    __syncthreads();

    // ---------------- out = T @ W9 + b9 + x ----------------
    gemm_f(g_W9f, sG, acc, lane, r0, nb);
    #pragma unroll
    for (int mt = 0; mt < 2; mt++)
        #pragma unroll
        for (int nt = 0; nt < 8; nt++) {
            int col = nb + nt * 8 + tig * 2;
            float b0v = sBias[col], b1v = sBias[col + 1];
            int ra = r0 + mt * 16 + grp, rb = ra + 8;
            float2 xa = *(const float2*)(xrow + ra * CH + col);
            float2 xb = *(const float2*)(xrow + rb * CH + col);
            *(float2*)(orow + ra * CH + col) =
                make_float2(acc[mt][nt][0] + b0v + xa.x, acc[mt][nt][1] + b1v + xa.y);
            *(float2*)(orow + rb * CH + col) =
                make_float2(acc[mt][nt][2] + b0v + xb.x, acc[mt][nt][3] + b1v + xb.y);
        }
}

extern "C" void kernel_launch(void* const* d_in, const int* in_sizes, int n_in,
                              void* d_out, int out_size) {
    const float* x  = (const float*)d_in[0];
    const float* Wq = (const float*)d_in[1];
    const float* bq = (const float*)d_in[2];
    const float* Wk = (const float*)d_in[3];
    const float* bk = (const float*)d_in[4];
    const float* Wv = (const float*)d_in[5];
    const float* bv = (const float*)d_in[6];
    const float* Wo = (const float*)d_in[7];
    const float* bo = (const float*)d_in[8];
    float* out = (float*)d_out;

    dim3 g8(8, 8, 3);
    setup_gemm_kernel<<<g8, 256>>>(Wq, Wk, Wv, Wo, bq, bk, bv, bo);

    cudaFuncSetAttribute(attn_kernel, cudaFuncAttributeMaxDynamicSharedMemorySize, SMEM_BYTES);
    attn_kernel<<<2048, 256, SMEM_BYTES>>>(x, out);
}

// round 11
// speedup vs baseline: 1.4717x; 1.2042x over previous
#include <cuda_runtime.h>
#include <cuda_bf16.h>
#include <cstdint>

// AttentionBlock fused kernel, sm_103a. Round 10:
// attn kernel identical to R9 (fragment-order weights from L2 + prefetch).
// Setup rewritten: single-shot smem staging (no per-chunk syncs) + properly
// parallel/coalesced vector precomputations. Setup ~47us -> ~6us.

#define CH    256
#define LDH   264   // bf16 tile row stride in halves
#define LDP   72    // bf16 P tile stride

// Fused weights in fragment order: uint2 per lane per (n8, k16) tile.
// idx_uint2 = (n8*16 + k16)*32 + lane;  v.x = {B[k0+2t][n], B[k0+2t+1][n]}, v.y = k+8 pair.
__device__ uint2 g_M8f[32 * 16 * 32];   // Wq @ Wk^T  (k = a-dim, n = b-dim)
__device__ uint2 g_W9f[32 * 16 * 32];   // Wv @ Wo
__device__ float g_b9[CH];              // bv @ Wo + bo
__device__ float g_w8[CH];              // Wk @ bq
__device__ float g_s8;                  // bk . bq

// Dynamic smem: As [32][256] fp32 (8192 f) + Bs [256][33] fp32 (8448 f)
#define SETUP_SMEM_FLOATS (8192 + 8448)
#define SETUP_SMEM_BYTES  (SETUP_SMEM_FLOATS * 4)

// ---- setup: z in {0,1}: fused weight GEMMs -> fragment scatter; z==2: vectors ----
__global__ void setup_kernel(const float* __restrict__ Wq, const float* __restrict__ Wk,
                             const float* __restrict__ Wv, const float* __restrict__ Wo,
                             const float* __restrict__ bq, const float* __restrict__ bk,
                             const float* __restrict__ bv, const float* __restrict__ bo) {
    extern __shared__ float sdyn[];
    const int tid = threadIdx.x;
    const int z = blockIdx.z;

    if (z == 2) {
        const int id = blockIdx.y * 8 + blockIdx.x;
        if (id < 8) {
            // w8[r] = sum_d Wk[r][d] * bq[d]; 8 threads per row, coalesced-ish
            int r = id * 32 + (tid >> 3);
            int q = tid & 7;
            const float4* wk = (const float4*)(Wk + r * CH + q * 32);
            float s = 0.f;
            #pragma unroll
            for (int j = 0; j < 8; j++) {
                float4 v = wk[j];
                int d = q * 32 + j * 4;
                s += v.x * bq[d] + v.y * bq[d + 1] + v.z * bq[d + 2] + v.w * bq[d + 3];
            }
            s += __shfl_xor_sync(0xffffffffu, s, 1);
            s += __shfl_xor_sync(0xffffffffu, s, 2);
            s += __shfl_xor_sync(0xffffffffu, s, 4);
            if (q == 0) g_w8[r] = s;
        } else if (id == 8) {
            // s8 = bk . bq
            float p = bk[tid] * bq[tid];
            #pragma unroll
            for (int d = 16; d > 0; d >>= 1) p += __shfl_xor_sync(0xffffffffu, p, d);
            if ((tid & 31) == 0) sdyn[tid >> 5] = p;
            __syncthreads();
            if (tid == 0) {
                float s = 0.f;
                #pragma unroll
                for (int w = 0; w < 8; w++) s += sdyn[w];
                g_s8 = s;
            }
        } else if (id >= 16 && id < 24) {
            // b9[c] = sum_d bv[d] * Wo[d][c] + bo[c]; warp-coalesced column sums
            int c0 = (id - 16) * 32;
            int tx = tid & 31, ty = tid >> 5;
            int c = c0 + tx;
            float s = 0.f;
            #pragma unroll 8
            for (int i = 0; i < 32; i++) {
                int d = ty + 8 * i;
                s += bv[d] * Wo[d * CH + c];
            }
            sdyn[ty * 33 + tx] = s;
            __syncthreads();
            if (ty == 0) {
                float t = 0.f;
                #pragma unroll
                for (int w = 0; w < 8; w++) t += sdyn[w * 33 + tx];
                g_b9[c] = t + bo[c];
            }
        }
        return;
    }

    // ---- z in {0,1}: 32x32 tile of (z ? Wv@Wo : Wq@Wk^T), K=256 in one staging ----
    float* As = sdyn;              // [32][256]
    float* Bs = sdyn + 8192;       // [256][33]
    const int tx = tid & 31, ty = tid >> 5;
    const int a0 = blockIdx.y * 32, b0 = blockIdx.x * 32;
    const float* A = z ? Wv : Wq;

    // Stage A[a0+i][0..255]
    #pragma unroll
    for (int k = 0; k < 8; k++) {
        int idx = tid + k * 256;           // 2048 float4
        int i = idx >> 6, j = (idx & 63) * 4;
        float4 v = *(const float4*)(A + (a0 + i) * CH + j);
        As[i * 256 + j] = v.x; As[i * 256 + j + 1] = v.y;
        As[i * 256 + j + 2] = v.z; As[i * 256 + j + 3] = v.w;
    }
    // Stage Bs[dd][c]
    if (z == 0) {   // Bs[dd][c] = Wk[b0+c][dd]
        #pragma unroll
        for (int k = 0; k < 8; k++) {
            int idx = tid + k * 256;
            int i = idx >> 6, j = (idx & 63) * 4;
            float4 v = *(const float4*)(Wk + (b0 + i) * CH + j);
            Bs[j * 33 + i] = v.x; Bs[(j + 1) * 33 + i] = v.y;
            Bs[(j + 2) * 33 + i] = v.z; Bs[(j + 3) * 33 + i] = v.w;
        }
    } else {        // Bs[dd][c] = Wo[dd][b0+c]
        #pragma unroll
        for (int k = 0; k < 8; k++) {
            int idx = tid + k * 256;
            int j = idx >> 3, i4 = (idx & 7) * 4;
            float4 v = *(const float4*)(Wo + j * CH + b0 + i4);
            Bs[j * 33 + i4] = v.x; Bs[j * 33 + i4 + 1] = v.y;
            Bs[j * 33 + i4 + 2] = v.z; Bs[j * 33 + i4 + 3] = v.w;
        }
    }
    __syncthreads();

    float acc[4] = {0.f, 0.f, 0.f, 0.f};
    #pragma unroll 4
    for (int dd = 0; dd < 256; dd++) {
        float b = Bs[dd * 33 + tx];
        #pragma unroll
        for (int r = 0; r < 4; r++) acc[r] += As[(ty + 8 * r) * 256 + dd] * b;
    }

    __nv_bfloat16* dst = (__nv_bfloat16*)(z ? g_W9f : g_M8f);
    #pragma unroll
    for (int r = 0; r < 4; r++) {
        int a = a0 + ty + 8 * r;          // k-dim
        int b = b0 + tx;                  // n-dim
        int idx = ((((b >> 3) * 16 + (a >> 4)) * 32) + (b & 7) * 4 + ((a & 7) >> 1)) * 4
                + ((a >> 3) & 1) * 2 + (a & 1);
        dst[idx] = __float2bfloat16(acc[r]);
    }
}

// ---- mma.sync helpers ----
__device__ __forceinline__ uint32_t smem_u32(const void* p) {
    return (uint32_t)__cvta_generic_to_shared(p);
}
__device__ __forceinline__ void ldm_x4(uint32_t addr, uint32_t& a0, uint32_t& a1,
                                       uint32_t& a2, uint32_t& a3) {
    asm volatile("ldmatrix.sync.aligned.m8n8.x4.shared.b16 {%0,%1,%2,%3}, [%4];"
                 : "=r"(a0), "=r"(a1), "=r"(a2), "=r"(a3) : "r"(addr));
}
__device__ __forceinline__ void ldm_x4t(uint32_t addr, uint32_t& b0, uint32_t& b1,
                                        uint32_t& b2, uint32_t& b3) {
    asm volatile("ldmatrix.sync.aligned.m8n8.x4.trans.shared.b16 {%0,%1,%2,%3}, [%4];"
                 : "=r"(b0), "=r"(b1), "=r"(b2), "=r"(b3) : "r"(addr));
}
__device__ __forceinline__ void mma_bf16(float c[4],
                                         uint32_t a0, uint32_t a1, uint32_t a2, uint32_t a3,
                                         uint32_t b0, uint32_t b1) {
    asm volatile("mma.sync.aligned.m16n8k16.row.col.f32.bf16.bf16.f32 "
                 "{%0,%1,%2,%3}, {%4,%5,%6,%7}, {%8,%9}, {%0,%1,%2,%3};"
                 : "+f"(c[0]), "+f"(c[1]), "+f"(c[2]), "+f"(c[3])
                 : "r"(a0), "r"(a1), "r"(a2), "r"(a3), "r"(b0), "r"(b1));
}

// GEMM, B from L2 fragments with next-step prefetch:
// acc[32x64] = A[64x256](smem) @ W(frag gmem).
__device__ __forceinline__ void gemm_f(const uint2* __restrict__ Wf,
                                       const __nv_bfloat16* sA,
                                       float acc[2][8][4],
                                       int lane, int r0, int nb) {
    #pragma unroll
    for (int mt = 0; mt < 2; mt++)
        #pragma unroll
        for (int nt = 0; nt < 8; nt++)
            acc[mt][nt][0] = acc[mt][nt][1] = acc[mt][nt][2] = acc[mt][nt][3] = 0.f;

    const uint2* wb = Wf + ((nb >> 3) * 16) * 32 + lane;
    uint2 vc[8], vn[8];
    #pragma unroll
    for (int nt = 0; nt < 8; nt++) vc[nt] = wb[(nt * 16) * 32];

    #pragma unroll
    for (int ks = 0; ks < 16; ks++) {
        if (ks < 15) {
            #pragma unroll
            for (int nt = 0; nt < 8; nt++) vn[nt] = wb[(nt * 16 + ks + 1) * 32];
        }
        uint32_t a[2][4];
        #pragma unroll
        for (int mt = 0; mt < 2; mt++)
            ldm_x4(smem_u32(sA + (r0 + mt * 16 + (lane & 15)) * LDH
                            + ks * 16 + ((lane >> 4) << 3)),
                   a[mt][0], a[mt][1], a[mt][2], a[mt][3]);
        #pragma unroll
        for (int nt = 0; nt < 8; nt++) {
            mma_bf16(acc[0][nt], a[0][0], a[0][1], a[0][2], a[0][3], vc[nt].x, vc[nt].y);
            mma_bf16(acc[1][nt], a[1][0], a[1][1], a[1][2], a[1][3], vc[nt].x, vc[nt].y);
        }
        if (ks < 15) {
            #pragma unroll
            for (int nt = 0; nt < 8; nt++) vc[nt] = vn[nt];
        }
    }
}

// SMEM: sX 33792 + sG 33792 + sP 9216 + sC 256 + sBias 1024 = 78080
#define SMEM_BYTES 78080

__global__ void __launch_bounds__(256, 2)
attn_kernel(const float* __restrict__ x, float* __restrict__ out)
{
    extern __shared__ char smem_raw[];
    __nv_bfloat16* sX  = (__nv_bfloat16*)smem_raw;           // [64][LDH]
    __nv_bfloat16* sG  = sX + 64 * LDH;                      // [64][LDH]
    __nv_bfloat16* sP  = sG + 64 * LDH;                      // [64][LDP]
    float*         sC  = (float*)(sP + 64 * LDP);            // [64]
    float*      sBias  = sC + 64;                            // [256]

    const int tid  = threadIdx.x;
    const int wid  = tid >> 5;
    const int lane = tid & 31;
    const int grp  = lane >> 2;
    const int tig  = lane & 3;

    const size_t base = (size_t)blockIdx.x * 64 * CH;
    const float* xrow = x   + base;
    float*       orow = out + base;

    // ---------------- Phase 0: bias + x tile (fp32 -> bf16) + c_j ----------------
    sBias[tid] = g_b9[tid];
    {
        const float4* xv = (const float4*)xrow;
        #pragma unroll
        for (int t = 0; t < 16; t++) {
            int i = tid + t * 256;             // 4096 float4
            int row = i >> 6;
            int colf = (i & 63) * 4;
            float4 v = xv[i];
            __nv_bfloat162* d = (__nv_bfloat162*)(sX + row * LDH + colf);
            d[0] = __floats2bfloat162_rn(v.x, v.y);
            d[1] = __floats2bfloat162_rn(v.z, v.w);
        }
    }
    // c_j = x_j . w8 + s8  (4 threads per row)
    {
        int row = tid >> 2, q = tid & 3;
        const float4* xv = (const float4*)(xrow + row * CH + q * 64);
        float s = 0.f;
        #pragma unroll
        for (int j = 0; j < 16; j++) {
            float4 v = xv[j];
            int c = q * 64 + j * 4;
            s += v.x * g_w8[c] + v.y * g_w8[c + 1] + v.z * g_w8[c + 2] + v.w * g_w8[c + 3];
        }
        s += __shfl_xor_sync(0xffffffffu, s, 1);
        s += __shfl_xor_sync(0xffffffffu, s, 2);
        if (q == 0) sC[row] = s + g_s8;
    }
    __syncthreads();

    const int r0 = (wid >> 2) * 32;   // warp's 32 rows
    const int nb = (wid & 3) * 64;    // warp's 64 cols

    float acc[2][8][4];

    // ---------------- G = X @ M8 -> sG ----------------
    gemm_f(g_M8f, sX, acc, lane, r0, nb);
    #pragma unroll
    for (int mt = 0; mt < 2; mt++)
        #pragma unroll
        for (int nt = 0; nt < 8; nt++) {
            int col = nb + nt * 8 + tig * 2;
            int ra = r0 + mt * 16 + grp;
            *(__nv_bfloat162*)(sG + ra * LDH + col) =
                __floats2bfloat162_rn(acc[mt][nt][0], acc[mt][nt][1]);
            *(__nv_bfloat162*)(sG + (ra + 8) * LDH + col) =
                __floats2bfloat162_rn(acc[mt][nt][2], acc[mt][nt][3]);
        }
    __syncthreads();

    // ---------------- S = (G X^T + c_j)*scale, softmax -> P (warps 0-3) ----
    if (wid < 4) {
        const int r0s = wid * 16;     // 16 rows, all 64 cols
        float sa[8][4];
        #pragma unroll
        for (int nt = 0; nt < 8; nt++)
            sa[nt][0] = sa[nt][1] = sa[nt][2] = sa[nt][3] = 0.f;
        #pragma unroll
        for (int ks = 0; ks < 16; ks++) {
            uint32_t a0, a1, a2, a3;
            ldm_x4(smem_u32(sG + (r0s + (lane & 15)) * LDH + ks * 16 + ((lane >> 4) << 3)),
                   a0, a1, a2, a3);
            #pragma unroll
            for (int nt16 = 0; nt16 < 2; nt16++) {
                uint32_t b0, b1, b2, b3;
                ldm_x4(smem_u32(sX + (nt16 * 32 + ((lane >> 4) << 3) + (lane & 7)) * LDH
                                + ks * 16 + (((lane >> 3) & 1) << 3)),
                       b0, b1, b2, b3);
                mma_bf16(sa[4 * nt16],     a0, a1, a2, a3, b0, b1);
                mma_bf16(sa[4 * nt16 + 1], a0, a1, a2, a3, b2, b3);
                uint32_t c0, c1, c2, c3;
                ldm_x4(smem_u32(sX + (nt16 * 32 + 16 + ((lane >> 4) << 3) + (lane & 7)) * LDH
                                + ks * 16 + (((lane >> 3) & 1) << 3)),
                       c0, c1, c2, c3);
                mma_bf16(sa[4 * nt16 + 2], a0, a1, a2, a3, c0, c1);
                mma_bf16(sa[4 * nt16 + 3], a0, a1, a2, a3, c2, c3);
            }
        }
        const float SCALE = 1.0f / (256.0f * 16.0f * 0.70710678118654752f);
        float v0[16], v1[16];
        #pragma unroll
        for (int nt = 0; nt < 8; nt++) {
            int col = nt * 8 + tig * 2;
            float c0 = sC[col], c1 = sC[col + 1];
            v0[2 * nt] = (sa[nt][0] + c0) * SCALE; v0[2 * nt + 1] = (sa[nt][1] + c1) * SCALE;
            v1[2 * nt] = (sa[nt][2] + c0) * SCALE; v1[2 * nt + 1] = (sa[nt][3] + c1) * SCALE;
        }
        float m0 = v0[0], m1 = v1[0];
        #pragma unroll
        for (int i = 1; i < 16; i++) { m0 = fmaxf(m0, v0[i]); m1 = fmaxf(m1, v1[i]); }
        m0 = fmaxf(m0, __shfl_xor_sync(0xffffffffu, m0, 1));
        m0 = fmaxf(m0, __shfl_xor_sync(0xffffffffu, m0, 2));
        m1 = fmaxf(m1, __shfl_xor_sync(0xffffffffu, m1, 1));
        m1 = fmaxf(m1, __shfl_xor_sync(0xffffffffu, m1, 2));
        float s0 = 0.f, s1 = 0.f;
        #pragma unroll
        for (int i = 0; i < 16; i++) {
            v0[i] = __expf(v0[i] - m0); s0 += v0[i];
            v1[i] = __expf(v1[i] - m1); s1 += v1[i];
        }
        s0 += __shfl_xor_sync(0xffffffffu, s0, 1);
        s0 += __shfl_xor_sync(0xffffffffu, s0, 2);
        s1 += __shfl_xor_sync(0xffffffffu, s1, 1);
        s1 += __shfl_xor_sync(0xffffffffu, s1, 2);
        float i0 = 1.0f / s0, i1 = 1.0f / s1;
        int ra = r0s + grp, rb = ra + 8;
        #pragma unroll
        for (int nt = 0; nt < 8; nt++) {
            *(__nv_bfloat162*)(sP + ra * LDP + nt * 8 + tig * 2) =
                __floats2bfloat162_rn(v0[2 * nt] * i0, v0[2 * nt + 1] * i0);
            *(__nv_bfloat162*)(sP + rb * LDP + nt * 8 + tig * 2) =
                __floats2bfloat162_rn(v1[2 * nt] * i1, v1[2 * nt + 1] * i1);
        }
    }
    __syncthreads();

    // ---------------- T = P @ X -> sG (G dead after S) ----------------
    {
        #pragma unroll
        for (int mt = 0; mt < 2; mt++)
            #pragma unroll
            for (int nt = 0; nt < 8; nt++)
                acc[mt][nt][0] = acc[mt][nt][1] = acc[mt][nt][2] = acc[mt][nt][3] = 0.f;
        #pragma unroll
        for (int ks = 0; ks < 4; ks++) {
            uint32_t a[2][4];
            #pragma unroll
            for (int mt = 0; mt < 2; mt++)
                ldm_x4(smem_u32(sP + (r0 + mt * 16 + (lane & 15)) * LDP
                                + ks * 16 + ((lane >> 4) << 3)),
                       a[mt][0], a[mt][1], a[mt][2], a[mt][3]);
            #pragma unroll
            for (int nt16 = 0; nt16 < 4; nt16++) {
                uint32_t b0, b1, b2, b3;
                ldm_x4t(smem_u32(sX + (ks * 16 + (lane & 15)) * LDH
                                 + nb + nt16 * 16 + ((lane >> 4) << 3)),
                        b0, b1, b2, b3);
                #pragma unroll
                for (int mt = 0; mt < 2; mt++) {
                    mma_bf16(acc[mt][2 * nt16],     a[mt][0], a[mt][1], a[mt][2], a[mt][3], b0, b1);
                    mma_bf16(acc[mt][2 * nt16 + 1], a[mt][0], a[mt][1], a[mt][2], a[mt][3], b2, b3);
                }
            }
        }
        __syncthreads();   // all S-phase reads of sG complete before overwrite
        #pragma unroll
        for (int mt = 0; mt < 2; mt++)
            #pragma unroll
            for (int nt = 0; nt < 8; nt++) {
                int col = nb + nt * 8 + tig * 2;
                int ra = r0 + mt * 16 + grp;
                *(__nv_bfloat162*)(sG + ra * LDH + col) =
                    __floats2bfloat162_rn(acc[mt][nt][0], acc[mt][nt][1]);
                *(__nv_bfloat162*)(sG + (ra + 8) * LDH + col) =
                    __floats2bfloat162_rn(acc[mt][nt][2], acc[mt][nt][3]);
            }
    }
    __syncthreads();

    // ---------------- out = T @ W9 + b9 + x ----------------
    gemm_f(g_W9f, sG, acc, lane, r0, nb);
    #pragma unroll
    for (int mt = 0; mt < 2; mt++)
        #pragma unroll
        for (int nt = 0; nt < 8; nt++) {
            int col = nb + nt * 8 + tig * 2;
            float b0v = sBias[col], b1v = sBias[col + 1];
            int ra = r0 + mt * 16 + grp, rb = ra + 8;
            float2 xa = *(const float2*)(xrow + ra * CH + col);
            float2 xb = *(const float2*)(xrow + rb * CH + col);
            *(float2*)(orow + ra * CH + col) =
                make_float2(acc[mt][nt][0] + b0v + xa.x, acc[mt][nt][1] + b1v + xa.y);
            *(float2*)(orow + rb * CH + col) =
                make_float2(acc[mt][nt][2] + b0v + xb.x, acc[mt][nt][3] + b1v + xb.y);
        }
}

extern "C" void kernel_launch(void* const* d_in, const int* in_sizes, int n_in,
                              void* d_out, int out_size) {
    const float* x  = (const float*)d_in[0];
    const float* Wq = (const float*)d_in[1];
    const float* bq = (const float*)d_in[2];
    const float* Wk = (const float*)d_in[3];
    const float* bk = (const float*)d_in[4];
    const float* Wv = (const float*)d_in[5];
    const float* bv = (const float*)d_in[6];
    const float* Wo = (const float*)d_in[7];
    const float* bo = (const float*)d_in[8];
    float* out = (float*)d_out;

    cudaFuncSetAttribute(setup_kernel, cudaFuncAttributeMaxDynamicSharedMemorySize,
                         SETUP_SMEM_BYTES);
    setup_kernel<<<dim3(8, 8, 3), 256, SETUP_SMEM_BYTES>>>(Wq, Wk, Wv, Wo, bq, bk, bv, bo);

    cudaFuncSetAttribute(attn_kernel, cudaFuncAttributeMaxDynamicSharedMemorySize, SMEM_BYTES);
    attn_kernel<<<2048, 256, SMEM_BYTES>>>(x, out);
}